// round 1
// baseline (speedup 1.0000x reference)
#include <cuda_runtime.h>
#include <cuda_fp16.h>

#define BB 4
#define TT 1024
#define HH 27
#define WW 48
#define NPIX (HH*WW)          // 1296
#define NBINS 512
#define LOOKUP 101
#define PAD 50
#define OUT_DIM 128
#define TB 32
#define WINROWS (TB + 2*PAD)  // 132

// 8 MB scratch for normalized histograms (fp32): [B*T][NBINS]
__device__ float g_hist[BB*TT*NBINS];

// ---------------------------------------------------------------------------
// Kernel 1: per-frame 512-bin color histogram + L2 normalization
// One block per frame (B*T = 4096 blocks), 256 threads.
// ---------------------------------------------------------------------------
__global__ __launch_bounds__(256) void hist_kernel(const int* __restrict__ frames) {
    __shared__ int sh[NBINS];
    __shared__ float ssq[8];
    const int f = blockIdx.x;
    const int tid = threadIdx.x;

    sh[tid] = 0;
    sh[tid + 256] = 0;
    __syncthreads();

    const int* fp = frames + (long long)f * (NPIX * 3);
    for (int p = tid; p < NPIX; p += 256) {
        int r = fp[3*p + 0];
        int g = fp[3*p + 1];
        int b = fp[3*p + 2];
        int bin = ((r >> 5) << 6) | ((g >> 5) << 3) | (b >> 5);
        atomicAdd(&sh[bin], 1);
    }
    __syncthreads();

    float c0 = (float)sh[tid];
    float c1 = (float)sh[tid + 256];
    float s = c0*c0 + c1*c1;
    #pragma unroll
    for (int o = 16; o; o >>= 1) s += __shfl_xor_sync(0xffffffffu, s, o);
    if ((tid & 31) == 0) ssq[tid >> 5] = s;
    __syncthreads();
    if (tid < 8) {
        float v = ssq[tid];
        #pragma unroll
        for (int o = 4; o; o >>= 1) v += __shfl_xor_sync(0xffu, v, o);
        if (tid == 0) ssq[0] = v;
    }
    __syncthreads();

    float norm = sqrtf(ssq[0]);
    float scale = 1.0f / fmaxf(norm, 1e-12f);
    float* outp = g_hist + (long long)f * NBINS;
    outp[tid]       = c0 * scale;
    outp[tid + 256] = c1 * scale;
}

// ---------------------------------------------------------------------------
// Kernel 2: fused band self-similarity (window 101) + FC(101->128) + ReLU
// Grid (T/TB, B) = (32, 4) = 128 blocks, 256 threads.
// Dynamic smem: fp16 window [WINROWS][512] + win scratch + fc_w fp32.
// ---------------------------------------------------------------------------
#define SWIN_STRIDE 104
#define SMEM_WIN_BYTES   (WINROWS * NBINS * 2)            // 135168
#define SMEM_SWIN_BYTES  (TB * SWIN_STRIDE * 4)           // 13312
#define SMEM_FC_BYTES    (LOOKUP * OUT_DIM * 4)           // 51712
#define SMEM_TOTAL (SMEM_WIN_BYTES + SMEM_SWIN_BYTES + SMEM_FC_BYTES) // 200192

__global__ __launch_bounds__(256, 1) void band_fc_kernel(
    const float* __restrict__ fc_w,
    const float* __restrict__ fc_b,
    float* __restrict__ out)
{
    extern __shared__ char smem[];
    __half* swh  = (__half*)smem;                               // [WINROWS][NBINS]
    float*  swin = (float*)(smem + SMEM_WIN_BYTES);             // [TB][SWIN_STRIDE]
    float*  sfc  = (float*)(smem + SMEM_WIN_BYTES + SMEM_SWIN_BYTES); // [101][128]

    const int tid = threadIdx.x;
    const int b   = blockIdx.y;
    const int t0  = blockIdx.x * TB;

    // ---- Phase 1: load fp32 hist window -> fp16 smem (zero outside [0,T)) ----
    const float* hb = g_hist + (long long)b * TT * NBINS;
    for (int idx = tid; idx < WINROWS * (NBINS/4); idx += 256) {
        int row  = idx / (NBINS/4);
        int col4 = idx - row * (NBINS/4);
        int g = t0 - PAD + row;
        float4 v = make_float4(0.f, 0.f, 0.f, 0.f);
        if (g >= 0 && g < TT)
            v = ((const float4*)(hb + (long long)g * NBINS))[col4];
        __half2* dst = (__half2*)(swh + row * NBINS + col4 * 4);
        dst[0] = __floats2half2_rn(v.x, v.y);
        dst[1] = __floats2half2_rn(v.z, v.w);
    }
    for (int idx = tid; idx < LOOKUP * OUT_DIM; idx += 256)
        sfc[idx] = fc_w[idx];
    __syncthreads();

    // ---- Phase 2: banded dots. warp w handles tl = w, w+8, w+16, w+24 ----
    const unsigned* sw32 = (const unsigned*)swh;  // 256 uint (half2) words per row
    const int warp = tid >> 5;
    const int lane = tid & 31;

    for (int tl = warp; tl < TB; tl += 8) {
        // cache A row (global t = t0+tl -> window row tl+PAD) in fp32 registers
        float af[16];
        const unsigned* arow = sw32 + (tl + PAD) * (NBINS/2);
        #pragma unroll
        for (int i = 0; i < 8; i++) {
            float2 f = __half22float2(*(const __half2*)&arow[lane + 32*i]);
            af[2*i]   = f.x;
            af[2*i+1] = f.y;
        }
        for (int l = 0; l < LOOKUP; l++) {
            const unsigned* brow = sw32 + (tl + l) * (NBINS/2);
            float acc0 = 0.f, acc1 = 0.f;
            #pragma unroll
            for (int i = 0; i < 8; i++) {
                float2 f = __half22float2(*(const __half2*)&brow[lane + 32*i]);
                acc0 = fmaf(af[2*i],   f.x, acc0);
                acc1 = fmaf(af[2*i+1], f.y, acc1);
            }
            float acc = acc0 + acc1;
            #pragma unroll
            for (int o = 16; o; o >>= 1)
                acc += __shfl_xor_sync(0xffffffffu, acc, o);
            if (lane == 0) swin[tl * SWIN_STRIDE + l] = acc;
        }
    }
    __syncthreads();

    // ---- Phase 3: FC + bias + ReLU. thread -> (16 t's, one output channel) ----
    const int ox  = tid & 127;
    const int grp = tid >> 7;  // 0 or 1 -> t half
    const float bias = fc_b[ox];
    float accv[16];
    #pragma unroll
    for (int i = 0; i < 16; i++) accv[i] = bias;

    for (int l = 0; l < LOOKUP; l++) {
        float wv = sfc[l * OUT_DIM + ox];
        #pragma unroll
        for (int i = 0; i < 16; i++)
            accv[i] = fmaf(swin[(grp*16 + i) * SWIN_STRIDE + l], wv, accv[i]);
    }

    float* ob = out + ((long long)b * TT + t0 + grp*16) * OUT_DIM;
    #pragma unroll
    for (int i = 0; i < 16; i++)
        ob[i * OUT_DIM + ox] = fmaxf(accv[i], 0.f);
}

// ---------------------------------------------------------------------------
extern "C" void kernel_launch(void* const* d_in, const int* in_sizes, int n_in,
                              void* d_out, int out_size) {
    const int*   frames = (const int*)d_in[0];
    const float* fc_w   = (const float*)d_in[1];
    const float* fc_b   = (const float*)d_in[2];
    float* out = (float*)d_out;

    (void)in_sizes; (void)n_in; (void)out_size;

    cudaFuncSetAttribute(band_fc_kernel,
                         cudaFuncAttributeMaxDynamicSharedMemorySize, SMEM_TOTAL);

    hist_kernel<<<BB * TT, 256>>>(frames);
    band_fc_kernel<<<dim3(TT / TB, BB), 256, SMEM_TOTAL>>>(fc_w, fc_b, out);
}

// round 2
// speedup vs baseline: 4.8084x; 4.8084x over previous
#include <cuda_runtime.h>
#include <cuda_fp16.h>
#include <cstdint>

#define BB 4
#define TT 1024
#define NPIX 1296
#define NBINS 512
#define LOOKUP 101
#define PAD 50
#define OUT_DIM 128
#define TB 32
#define WROWS 136        // padded window rows (132 -> 136, 17 n-tiles of 8)
#define WSTRIDE 520      // halfs per window row (512 + 8) -> 1040B, ldmatrix conflict-free
#define SW_STRIDE 120    // halfs per row for swin / sfc (101 padded to 112, stride 120 -> 240B)

// 8 MB scratch for normalized histograms (fp32): [B*T][NBINS]
__device__ float g_hist[BB*TT*NBINS];

__device__ __forceinline__ uint32_t smem_u32(const void* p) {
    return (uint32_t)__cvta_generic_to_shared(p);
}

#define LDSM_X4(r0,r1,r2,r3,addr) \
    asm volatile("ldmatrix.sync.aligned.m8n8.x4.shared.b16 {%0,%1,%2,%3}, [%4];" \
        : "=r"(r0),"=r"(r1),"=r"(r2),"=r"(r3) : "r"(addr))
#define LDSM_X2(r0,r1,addr) \
    asm volatile("ldmatrix.sync.aligned.m8n8.x2.shared.b16 {%0,%1}, [%2];" \
        : "=r"(r0),"=r"(r1) : "r"(addr))
#define MMA16816(d, a0,a1,a2,a3, b0,b1) \
    asm volatile("mma.sync.aligned.m16n8k16.row.col.f32.f16.f16.f32 " \
        "{%0,%1,%2,%3}, {%4,%5,%6,%7}, {%8,%9}, {%0,%1,%2,%3};" \
        : "+f"(d[0]), "+f"(d[1]), "+f"(d[2]), "+f"(d[3]) \
        : "r"(a0),"r"(a1),"r"(a2),"r"(a3), "r"(b0),"r"(b1))

// ---------------------------------------------------------------------------
// Kernel 1: per-frame 512-bin color histogram + L2 normalization
// One block per frame (B*T = 4096 blocks), 256 threads. int4-vectorized loads.
// ---------------------------------------------------------------------------
__global__ __launch_bounds__(256) void hist_kernel(const int* __restrict__ frames) {
    __shared__ int sh[NBINS];
    __shared__ float ssq[8];
    const int f = blockIdx.x;
    const int tid = threadIdx.x;

    sh[tid] = 0;
    sh[tid + 256] = 0;
    __syncthreads();

    // 1296 pixels = 324 groups of 4 pixels = 3 int4 per group
    const int4* fp4 = (const int4*)(frames + (long long)f * (NPIX * 3));
    for (int g = tid; g < NPIX/4; g += 256) {
        int4 w0 = fp4[3*g + 0];
        int4 w1 = fp4[3*g + 1];
        int4 w2 = fp4[3*g + 2];
        int b0 = ((w0.x >> 5) << 6) | ((w0.y >> 5) << 3) | (w0.z >> 5);
        int b1 = ((w0.w >> 5) << 6) | ((w1.x >> 5) << 3) | (w1.y >> 5);
        int b2 = ((w1.z >> 5) << 6) | ((w1.w >> 5) << 3) | (w2.x >> 5);
        int b3 = ((w2.y >> 5) << 6) | ((w2.z >> 5) << 3) | (w2.w >> 5);
        atomicAdd(&sh[b0], 1);
        atomicAdd(&sh[b1], 1);
        atomicAdd(&sh[b2], 1);
        atomicAdd(&sh[b3], 1);
    }
    __syncthreads();

    float c0 = (float)sh[tid];
    float c1 = (float)sh[tid + 256];
    float s = c0*c0 + c1*c1;
    #pragma unroll
    for (int o = 16; o; o >>= 1) s += __shfl_xor_sync(0xffffffffu, s, o);
    if ((tid & 31) == 0) ssq[tid >> 5] = s;
    __syncthreads();
    if (tid < 8) {
        float v = ssq[tid];
        #pragma unroll
        for (int o = 4; o; o >>= 1) v += __shfl_xor_sync(0xffu, v, o);
        if (tid == 0) ssq[0] = v;
    }
    __syncthreads();

    float scale = 1.0f / fmaxf(sqrtf(ssq[0]), 1e-12f);
    float* outp = g_hist + (long long)f * NBINS;
    outp[tid]       = c0 * scale;
    outp[tid + 256] = c1 * scale;
}

// ---------------------------------------------------------------------------
// Kernel 2: band sims + FC + ReLU, all on tensor cores (mma.sync fp16).
// Grid (32, 4) = 128 blocks, 256 threads (8 warps).
//   GEMM1: C[32 x 136] = A[32 x 512] * W[136 x 512]^T   (band extracted to swin)
//   GEMM2: O[32 x 128] = win[32 x 112] * fc_t[128 x 112]^T  (+bias, ReLU)
// ---------------------------------------------------------------------------
#define SMEM_WIN_BYTES  (WROWS * WSTRIDE * 2)           // 141440
#define SMEM_SWIN_BYTES (TB * SW_STRIDE * 2)            // 7680
#define SMEM_FC_BYTES   (OUT_DIM * SW_STRIDE * 2)       // 30720
#define SMEM_BIAS_BYTES (OUT_DIM * 4)                   // 512
#define SMEM_TOTAL (SMEM_WIN_BYTES + SMEM_SWIN_BYTES + SMEM_FC_BYTES + SMEM_BIAS_BYTES)

__global__ __launch_bounds__(256, 1) void band_fc_kernel(
    const float* __restrict__ fc_w,
    const float* __restrict__ fc_b,
    float* __restrict__ out)
{
    extern __shared__ char smem[];
    __half* swh  = (__half*)smem;                                        // [136][520]
    __half* swin = (__half*)(smem + SMEM_WIN_BYTES);                     // [32][120]
    __half* sfc  = (__half*)(smem + SMEM_WIN_BYTES + SMEM_SWIN_BYTES);   // [128][120] transposed fc_w
    float*  sbias= (float*)(smem + SMEM_WIN_BYTES + SMEM_SWIN_BYTES + SMEM_FC_BYTES);

    const int tid  = threadIdx.x;
    const int warp = tid >> 5;
    const int lane = tid & 31;
    const int b    = blockIdx.y;
    const int t0   = blockIdx.x * TB;

    // ---- Phase 1a: zero swin + sfc, load window fp32 -> fp16, copy bias ----
    for (int idx = tid; idx < TB * SW_STRIDE / 2; idx += 256)
        ((__half2*)swin)[idx] = __half2half2(__float2half(0.f));
    for (int idx = tid; idx < OUT_DIM * SW_STRIDE / 2; idx += 256)
        ((__half2*)sfc)[idx] = __half2half2(__float2half(0.f));
    if (tid < OUT_DIM) sbias[tid] = fc_b[tid];

    const float* hb = g_hist + (long long)b * TT * NBINS;
    for (int idx = tid; idx < WROWS * (NBINS/4); idx += 256) {
        int row  = idx >> 7;          // / 128
        int col4 = idx & 127;
        int g = t0 - PAD + row;
        float4 v = make_float4(0.f, 0.f, 0.f, 0.f);
        if (g >= 0 && g < TT)
            v = ((const float4*)(hb + (long long)g * NBINS))[col4];
        __half2* dst = (__half2*)(swh + row * WSTRIDE + col4 * 4);
        dst[0] = __floats2half2_rn(v.x, v.y);
        dst[1] = __floats2half2_rn(v.z, v.w);
    }
    __syncthreads();

    // ---- Phase 1b: fill transposed fc weights (zeros already synced) ----
    for (int idx = tid; idx < LOOKUP * OUT_DIM; idx += 256) {
        int l = idx >> 7;            // row of fc_w
        int o = idx & 127;           // out channel
        sfc[o * SW_STRIDE + l] = __float2half(fc_w[idx]);
    }

    // ---- Phase 2: GEMM1 on tensor cores ----
    {
        const int mtile = warp >> 2;            // 0..1
        const int nbase = warp & 3;             // n-tiles: nbase + 4j (17 total)
        const int ntcount = (nbase == 0) ? 5 : 4;
        float acc[5][4];
        #pragma unroll
        for (int j = 0; j < 5; j++)
            #pragma unroll
            for (int i = 0; i < 4; i++) acc[j][i] = 0.f;

        uint32_t a_base = smem_u32(swh) +
            (uint32_t)(((mtile*16 + (lane & 15) + PAD) * WSTRIDE + (lane >> 4) * 8) * 2);
        uint32_t b_base[5];
        #pragma unroll
        for (int j = 0; j < 5; j++) {
            int nt = nbase + 4*j; if (nt > 16) nt = 16;
            b_base[j] = smem_u32(swh) +
                (uint32_t)(((nt*8 + (lane & 7)) * WSTRIDE + ((lane >> 3) & 1) * 8) * 2);
        }

        for (int kk = 0; kk < NBINS/16; kk++) {
            uint32_t a0,a1,a2,a3;
            LDSM_X4(a0,a1,a2,a3, a_base + kk*32);
            #pragma unroll
            for (int j = 0; j < 5; j++) {
                if (j < ntcount) {
                    uint32_t p0,p1;
                    LDSM_X2(p0,p1, b_base[j] + kk*32);
                    MMA16816(acc[j], a0,a1,a2,a3, p0,p1);
                }
            }
        }

        // band extraction epilogue: swin[r][c - r] = C[r][c] for 0 <= c-r < 101
        int r0 = mtile*16 + (lane >> 2);
        int cb = 2*(lane & 3);
        #pragma unroll
        for (int j = 0; j < 5; j++) {
            if (j < ntcount) {
                int c0 = (nbase + 4*j)*8 + cb;
                int l;
                l = c0     - r0;     if ((unsigned)l < LOOKUP) swin[r0*SW_STRIDE + l]     = __float2half(acc[j][0]);
                l = c0 + 1 - r0;     if ((unsigned)l < LOOKUP) swin[r0*SW_STRIDE + l]     = __float2half(acc[j][1]);
                l = c0     - (r0+8); if ((unsigned)l < LOOKUP) swin[(r0+8)*SW_STRIDE + l] = __float2half(acc[j][2]);
                l = c0 + 1 - (r0+8); if ((unsigned)l < LOOKUP) swin[(r0+8)*SW_STRIDE + l] = __float2half(acc[j][3]);
            }
        }
    }
    __syncthreads();

    // ---- Phase 3: GEMM2 (FC) + bias + ReLU on tensor cores ----
    {
        const int mt = warp >> 2;               // 0..1
        const int nb = warp & 3;                // n-tiles: nb + 4j, j=0..3 (16 total)
        float acc[4][4];
        #pragma unroll
        for (int j = 0; j < 4; j++)
            #pragma unroll
            for (int i = 0; i < 4; i++) acc[j][i] = 0.f;

        uint32_t a_base = smem_u32(swin) +
            (uint32_t)(((mt*16 + (lane & 15)) * SW_STRIDE + (lane >> 4) * 8) * 2);
        uint32_t b_base[4];
        #pragma unroll
        for (int j = 0; j < 4; j++) {
            int nt = nb + 4*j;
            b_base[j] = smem_u32(sfc) +
                (uint32_t)(((nt*8 + (lane & 7)) * SW_STRIDE + ((lane >> 3) & 1) * 8) * 2);
        }

        #pragma unroll
        for (int kk = 0; kk < 7; kk++) {        // K = 112 (cols 101..111 are zero)
            uint32_t a0,a1,a2,a3;
            LDSM_X4(a0,a1,a2,a3, a_base + kk*32);
            #pragma unroll
            for (int j = 0; j < 4; j++) {
                uint32_t p0,p1;
                LDSM_X2(p0,p1, b_base[j] + kk*32);
                MMA16816(acc[j], a0,a1,a2,a3, p0,p1);
            }
        }

        int r0 = mt*16 + (lane >> 2);
        int cb = 2*(lane & 3);
        float* obase = out + ((long long)(b * TT + t0 + r0)) * OUT_DIM;
        #pragma unroll
        for (int j = 0; j < 4; j++) {
            int c0 = (nb + 4*j)*8 + cb;
            float bv0 = sbias[c0], bv1 = sbias[c0 + 1];
            float2 v0 = make_float2(fmaxf(acc[j][0] + bv0, 0.f), fmaxf(acc[j][1] + bv1, 0.f));
            float2 v1 = make_float2(fmaxf(acc[j][2] + bv0, 0.f), fmaxf(acc[j][3] + bv1, 0.f));
            *(float2*)(obase + c0)                = v0;
            *(float2*)(obase + 8*OUT_DIM + c0)    = v1;
        }
    }
}

// ---------------------------------------------------------------------------
extern "C" void kernel_launch(void* const* d_in, const int* in_sizes, int n_in,
                              void* d_out, int out_size) {
    const int*   frames = (const int*)d_in[0];
    const float* fc_w   = (const float*)d_in[1];
    const float* fc_b   = (const float*)d_in[2];
    float* out = (float*)d_out;

    (void)in_sizes; (void)n_in; (void)out_size;

    cudaFuncSetAttribute(band_fc_kernel,
                         cudaFuncAttributeMaxDynamicSharedMemorySize, SMEM_TOTAL);

    hist_kernel<<<BB * TT, 256>>>(frames);
    band_fc_kernel<<<dim3(TT / TB, BB), 256, SMEM_TOTAL>>>(fc_w, fc_b, out);
}

// round 3
// speedup vs baseline: 5.7167x; 1.1889x over previous
#include <cuda_runtime.h>
#include <cuda_fp16.h>
#include <cstdint>

#define BB 4
#define TT 1024
#define NPIX 1296
#define NBINS 512
#define LOOKUP 101
#define PAD 50
#define OUT_DIM 128
#define TB 32
#define WROWS 136        // padded window rows (132 -> 136)
#define WSTRIDE 520      // halves per window row (1040B, 16B-aligned, ldsm conflict-free)
#define SW_STRIDE 120    // halves per swin row (240B)
#define FC_STRIDE 136    // halves per sfc row (272B)

// 4 MB scratch: normalized histograms in fp16 [B*T][NBINS]
__device__ __half g_hist[BB*TT*NBINS];

__device__ __forceinline__ uint32_t smem_u32(const void* p) {
    return (uint32_t)__cvta_generic_to_shared(p);
}

#define LDSM_X4(r0,r1,r2,r3,addr) \
    asm volatile("ldmatrix.sync.aligned.m8n8.x4.shared.b16 {%0,%1,%2,%3}, [%4];" \
        : "=r"(r0),"=r"(r1),"=r"(r2),"=r"(r3) : "r"(addr))
#define LDSM_X4T(r0,r1,r2,r3,addr) \
    asm volatile("ldmatrix.sync.aligned.m8n8.x4.trans.shared.b16 {%0,%1,%2,%3}, [%4];" \
        : "=r"(r0),"=r"(r1),"=r"(r2),"=r"(r3) : "r"(addr))
#define LDSM_X2(r0,r1,addr) \
    asm volatile("ldmatrix.sync.aligned.m8n8.x2.shared.b16 {%0,%1}, [%2];" \
        : "=r"(r0),"=r"(r1) : "r"(addr))
#define MMA16816(d, a0,a1,a2,a3, b0,b1) \
    asm volatile("mma.sync.aligned.m16n8k16.row.col.f32.f16.f16.f32 " \
        "{%0,%1,%2,%3}, {%4,%5,%6,%7}, {%8,%9}, {%0,%1,%2,%3};" \
        : "+f"(d[0]), "+f"(d[1]), "+f"(d[2]), "+f"(d[3]) \
        : "r"(a0),"r"(a1),"r"(a2),"r"(a3), "r"(b0),"r"(b1))
#define CP_ASYNC16(saddr, gaddr, srcsz) \
    asm volatile("cp.async.cg.shared.global [%0], [%1], 16, %2;" \
        :: "r"(saddr), "l"(gaddr), "r"(srcsz))

// ---------------------------------------------------------------------------
// Kernel 1: per-frame 512-bin histogram + L2 norm, fp16 output.
// ---------------------------------------------------------------------------
__global__ __launch_bounds__(256) void hist_kernel(const int* __restrict__ frames) {
    __shared__ int sh[NBINS];
    __shared__ float ssq[8];
    const int f = blockIdx.x;
    const int tid = threadIdx.x;

    sh[tid] = 0;
    sh[tid + 256] = 0;
    __syncthreads();

    const int4* fp4 = (const int4*)(frames + (long long)f * (NPIX * 3));
    for (int g = tid; g < NPIX/4; g += 256) {
        int4 w0 = fp4[3*g + 0];
        int4 w1 = fp4[3*g + 1];
        int4 w2 = fp4[3*g + 2];
        int b0 = ((w0.x >> 5) << 6) | ((w0.y >> 5) << 3) | (w0.z >> 5);
        int b1 = ((w0.w >> 5) << 6) | ((w1.x >> 5) << 3) | (w1.y >> 5);
        int b2 = ((w1.z >> 5) << 6) | ((w1.w >> 5) << 3) | (w2.x >> 5);
        int b3 = ((w2.y >> 5) << 6) | ((w2.z >> 5) << 3) | (w2.w >> 5);
        atomicAdd(&sh[b0], 1);
        atomicAdd(&sh[b1], 1);
        atomicAdd(&sh[b2], 1);
        atomicAdd(&sh[b3], 1);
    }
    __syncthreads();

    float c0 = (float)sh[tid];
    float c1 = (float)sh[tid + 256];
    float s = c0*c0 + c1*c1;
    #pragma unroll
    for (int o = 16; o; o >>= 1) s += __shfl_xor_sync(0xffffffffu, s, o);
    if ((tid & 31) == 0) ssq[tid >> 5] = s;
    __syncthreads();
    if (tid < 8) {
        float v = ssq[tid];
        #pragma unroll
        for (int o = 4; o; o >>= 1) v += __shfl_xor_sync(0xffu, v, o);
        if (tid == 0) ssq[0] = v;
    }
    __syncthreads();

    float scale = 1.0f / fmaxf(sqrtf(ssq[0]), 1e-12f);
    __half* outp = g_hist + (long long)f * NBINS;
    outp[tid]       = __float2half(c0 * scale);
    outp[tid + 256] = __float2half(c1 * scale);
}

// ---------------------------------------------------------------------------
// Kernel 2: band sims + FC + ReLU on mma.sync fp16.
// Grid (32, 4), 256 threads (8 warps).
// ---------------------------------------------------------------------------
#define SMEM_WIN_BYTES  (WROWS * WSTRIDE * 2)            // 141440
#define SMEM_SWIN_BYTES (TB * SW_STRIDE * 2)             // 7680
#define SMEM_FC_BYTES   (112 * FC_STRIDE * 2)            // 30464
#define SMEM_BIAS_BYTES (OUT_DIM * 4)
#define SMEM_TOTAL (SMEM_WIN_BYTES + SMEM_SWIN_BYTES + SMEM_FC_BYTES + SMEM_BIAS_BYTES)

__global__ __launch_bounds__(256, 1) void band_fc_kernel(
    const float* __restrict__ fc_w,
    const float* __restrict__ fc_b,
    float* __restrict__ out)
{
    extern __shared__ char smem[];
    __half* swh  = (__half*)smem;                                        // [136][520]
    __half* swin = (__half*)(smem + SMEM_WIN_BYTES);                     // [32][120]
    __half* sfc  = (__half*)(smem + SMEM_WIN_BYTES + SMEM_SWIN_BYTES);   // [112][136] natural [k][o]
    float*  sbias= (float*)(smem + SMEM_WIN_BYTES + SMEM_SWIN_BYTES + SMEM_FC_BYTES);

    const int tid  = threadIdx.x;
    const int warp = tid >> 5;
    const int lane = tid & 31;
    const int b    = blockIdx.y;
    const int t0   = blockIdx.x * TB;

    // ---- Phase 1a: issue all window cp.asyncs (fp16 rows, zfill OOB) ----
    const __half* hb = g_hist + (long long)b * TT * NBINS;
    {
        uint32_t sbase = smem_u32(swh);
        #pragma unroll
        for (int i = 0; i < 33; i++) {
            int idx = tid + i * 256;              // 132*64 = 8448 chunks
            if (idx < WROWS * 64) {
                int row   = idx >> 6;
                int chunk = idx & 63;
                int g = t0 - PAD + row;
                int inb = (g >= 0 && g < TT);
                const __half* gsrc = hb + ((long long)(inb ? g : 0) * NBINS) + chunk * 8;
                uint32_t sdst = sbase + (uint32_t)(row * (WSTRIDE*2) + chunk * 16);
                CP_ASYNC16(sdst, gsrc, inb ? 16 : 0);
            }
        }
        asm volatile("cp.async.commit_group;");
    }

    // ---- Phase 1b (overlaps cp.async): fc weights, zeros, bias ----
    // sfc natural layout [l][o], float4 -> 2x half2, coalesced.
    for (int idx = tid; idx < LOOKUP * 32; idx += 256) {
        int l  = idx >> 5;
        int o4 = idx & 31;
        float4 v = ((const float4*)(fc_w + l * OUT_DIM))[o4];
        __half2* dst = (__half2*)(sfc + l * FC_STRIDE + o4 * 4);
        dst[0] = __floats2half2_rn(v.x, v.y);
        dst[1] = __floats2half2_rn(v.z, v.w);
    }
    // zero pad rows 101..111 of sfc
    for (int idx = tid; idx < 11 * (FC_STRIDE/2); idx += 256) {
        int r = 101 + idx / (FC_STRIDE/2);
        int c = idx % (FC_STRIDE/2);
        ((__half2*)(sfc + r * FC_STRIDE))[c] = __half2half2(__float2half(0.f));
    }
    // zero swin (k-padding for GEMM2)
    for (int idx = tid; idx < TB * SW_STRIDE / 2; idx += 256)
        ((__half2*)swin)[idx] = __half2half2(__float2half(0.f));
    if (tid < OUT_DIM) sbias[tid] = fc_b[tid];

    asm volatile("cp.async.wait_group 0;");
    __syncthreads();

    // ---- Phase 2: GEMM1  C[32 x 136] = A[32x512] * W[136x512]^T ----
    {
        const int mtile = warp >> 2;     // 0..1
        const int wq    = warp & 3;
        const int nb    = wq * 4;        // tiles nb..nb+3 (+16 if wq==0)
        float acc[5][4];
        #pragma unroll
        for (int j = 0; j < 5; j++)
            #pragma unroll
            for (int i = 0; i < 4; i++) acc[j][i] = 0.f;

        uint32_t swh0 = smem_u32(swh);
        uint32_t a_base = swh0 +
            (uint32_t)(((mtile*16 + (lane & 15) + PAD) * WSTRIDE + (lane >> 4) * 8) * 2);
        uint32_t b_base[2];
        #pragma unroll
        for (int p = 0; p < 2; p++) {
            int nt = nb + 2*p;
            b_base[p] = swh0 + (uint32_t)(
                (((nt + ((lane >> 4) & 1)) * 8 + (lane & 7)) * WSTRIDE
                 + ((lane >> 3) & 1) * 8) * 2);
        }
        uint32_t b16 = swh0 + (uint32_t)(
            ((16*8 + (lane & 7)) * WSTRIDE + ((lane >> 3) & 1) * 8) * 2);

        for (int kk = 0; kk < NBINS/16; kk++) {
            uint32_t a0,a1,a2,a3, q0,q1,q2,q3;
            LDSM_X4(a0,a1,a2,a3, a_base + kk*32);
            LDSM_X4(q0,q1,q2,q3, b_base[0] + kk*32);
            MMA16816(acc[0], a0,a1,a2,a3, q0,q1);
            MMA16816(acc[1], a0,a1,a2,a3, q2,q3);
            LDSM_X4(q0,q1,q2,q3, b_base[1] + kk*32);
            MMA16816(acc[2], a0,a1,a2,a3, q0,q1);
            MMA16816(acc[3], a0,a1,a2,a3, q2,q3);
            if (wq == 0) {
                uint32_t p0,p1;
                LDSM_X2(p0,p1, b16 + kk*32);
                MMA16816(acc[4], a0,a1,a2,a3, p0,p1);
            }
        }

        // band extraction: swin[r][c-r] = C[r][c], 0 <= c-r < 101
        int r0 = mtile*16 + (lane >> 2);
        int cb = 2*(lane & 3);
        #pragma unroll
        for (int j = 0; j < 5; j++) {
            if (j < 4 || wq == 0) {
                int nt = (j < 4) ? (nb + j) : 16;
                int c0 = nt*8 + cb;
                int l;
                l = c0     - r0;     if ((unsigned)l < LOOKUP) swin[r0*SW_STRIDE + l]     = __float2half(acc[j][0]);
                l = c0 + 1 - r0;     if ((unsigned)l < LOOKUP) swin[r0*SW_STRIDE + l]     = __float2half(acc[j][1]);
                l = c0     - (r0+8); if ((unsigned)l < LOOKUP) swin[(r0+8)*SW_STRIDE + l] = __float2half(acc[j][2]);
                l = c0 + 1 - (r0+8); if ((unsigned)l < LOOKUP) swin[(r0+8)*SW_STRIDE + l] = __float2half(acc[j][3]);
            }
        }
    }
    __syncthreads();

    // ---- Phase 3: GEMM2  O[32x128] = win[32x112] * fc[112x128]  (+bias, ReLU)
    {
        const int mt  = warp >> 2;             // 0..1
        const int nb4 = (warp & 3) * 4;        // 4 adjacent n-tiles
        float acc[4][4];
        #pragma unroll
        for (int j = 0; j < 4; j++)
            #pragma unroll
            for (int i = 0; i < 4; i++) acc[j][i] = 0.f;

        uint32_t a_base = smem_u32(swin) +
            (uint32_t)(((mt*16 + (lane & 15)) * SW_STRIDE + (lane >> 4) * 8) * 2);
        // B via ldmatrix.trans from [k][o] natural layout; x4 covers 2 n-tiles
        uint32_t b_base[2];
        #pragma unroll
        for (int p = 0; p < 2; p++) {
            int nt = nb4 + 2*p;
            b_base[p] = smem_u32(sfc) + (uint32_t)(
                ((((lane >> 3) & 1) * 8 + (lane & 7)) * FC_STRIDE
                 + (nt + ((lane >> 4) & 1)) * 8) * 2);
        }

        #pragma unroll
        for (int kk = 0; kk < 7; kk++) {       // K = 112
            uint32_t a0,a1,a2,a3, q0,q1,q2,q3;
            LDSM_X4(a0,a1,a2,a3, a_base + kk*32);
            uint32_t bko = (uint32_t)(kk * 16 * FC_STRIDE * 2);
            LDSM_X4T(q0,q1,q2,q3, b_base[0] + bko);
            MMA16816(acc[0], a0,a1,a2,a3, q0,q1);
            MMA16816(acc[1], a0,a1,a2,a3, q2,q3);
            LDSM_X4T(q0,q1,q2,q3, b_base[1] + bko);
            MMA16816(acc[2], a0,a1,a2,a3, q0,q1);
            MMA16816(acc[3], a0,a1,a2,a3, q2,q3);
        }

        int r0 = mt*16 + (lane >> 2);
        int cb = 2*(lane & 3);
        float* obase = out + ((long long)(b * TT + t0 + r0)) * OUT_DIM;
        #pragma unroll
        for (int j = 0; j < 4; j++) {
            int c0 = (nb4 + j)*8 + cb;
            float bv0 = sbias[c0], bv1 = sbias[c0 + 1];
            float2 v0 = make_float2(fmaxf(acc[j][0] + bv0, 0.f), fmaxf(acc[j][1] + bv1, 0.f));
            float2 v1 = make_float2(fmaxf(acc[j][2] + bv0, 0.f), fmaxf(acc[j][3] + bv1, 0.f));
            *(float2*)(obase + c0)             = v0;
            *(float2*)(obase + 8*OUT_DIM + c0) = v1;
        }
    }
}

// ---------------------------------------------------------------------------
extern "C" void kernel_launch(void* const* d_in, const int* in_sizes, int n_in,
                              void* d_out, int out_size) {
    const int*   frames = (const int*)d_in[0];
    const float* fc_w   = (const float*)d_in[1];
    const float* fc_b   = (const float*)d_in[2];
    float* out = (float*)d_out;

    (void)in_sizes; (void)n_in; (void)out_size;

    cudaFuncSetAttribute(band_fc_kernel,
                         cudaFuncAttributeMaxDynamicSharedMemorySize, SMEM_TOTAL);

    hist_kernel<<<BB * TT, 256>>>(frames);
    band_fc_kernel<<<dim3(TT / TB, BB), 256, SMEM_TOTAL>>>(fc_w, fc_b, out);
}

// round 5
// speedup vs baseline: 6.1802x; 1.0811x over previous
#include <cuda_runtime.h>
#include <cuda_fp16.h>
#include <cstdint>

#define BB 4
#define TT 1024
#define NPIX 1296
#define NBINS 512
#define LOOKUP 101
#define PAD 50
#define OUT_DIM 128
#define TB 28
#define NCHUNK 37        // ceil(1024/28)
#define WROWS 128        // TB + 2*PAD = 128 exactly
#define WSTRIDE 520      // halves per window row (1040B, ldsm conflict-free)
#define SW_STRIDE 120    // halves per swin row
#define FC_STRIDE 136    // halves per sfc row

// 4 MB scratch: normalized histograms in fp16 [B*T][NBINS]
__device__ __half g_hist[BB*TT*NBINS];

__device__ __forceinline__ uint32_t smem_u32(const void* p) {
    return (uint32_t)__cvta_generic_to_shared(p);
}

#define LDSM_X4(r0,r1,r2,r3,addr) \
    asm volatile("ldmatrix.sync.aligned.m8n8.x4.shared.b16 {%0,%1,%2,%3}, [%4];" \
        : "=r"(r0),"=r"(r1),"=r"(r2),"=r"(r3) : "r"(addr))
#define LDSM_X4T(r0,r1,r2,r3,addr) \
    asm volatile("ldmatrix.sync.aligned.m8n8.x4.trans.shared.b16 {%0,%1,%2,%3}, [%4];" \
        : "=r"(r0),"=r"(r1),"=r"(r2),"=r"(r3) : "r"(addr))
#define MMA16816(d, a0,a1,a2,a3, b0,b1) \
    asm volatile("mma.sync.aligned.m16n8k16.row.col.f32.f16.f16.f32 " \
        "{%0,%1,%2,%3}, {%4,%5,%6,%7}, {%8,%9}, {%0,%1,%2,%3};" \
        : "+f"(d[0]), "+f"(d[1]), "+f"(d[2]), "+f"(d[3]) \
        : "r"(a0),"r"(a1),"r"(a2),"r"(a3), "r"(b0),"r"(b1))
#define CP_ASYNC16(saddr, gaddr, srcsz) \
    asm volatile("cp.async.cg.shared.global [%0], [%1], 16, %2;" \
        :: "r"(saddr), "l"(gaddr), "r"(srcsz))

// ---------------------------------------------------------------------------
// Kernel 1: per-frame 512-bin histogram + L2 norm, fp16 output. (at HBM roofline)
// ---------------------------------------------------------------------------
__global__ __launch_bounds__(256) void hist_kernel(const int* __restrict__ frames) {
    __shared__ int sh[NBINS];
    __shared__ float ssq[8];
    const int f = blockIdx.x;
    const int tid = threadIdx.x;

    sh[tid] = 0;
    sh[tid + 256] = 0;
    __syncthreads();

    const int4* fp4 = (const int4*)(frames + (long long)f * (NPIX * 3));
    for (int g = tid; g < NPIX/4; g += 256) {
        int4 w0 = fp4[3*g + 0];
        int4 w1 = fp4[3*g + 1];
        int4 w2 = fp4[3*g + 2];
        int b0 = ((w0.x >> 5) << 6) | ((w0.y >> 5) << 3) | (w0.z >> 5);
        int b1 = ((w0.w >> 5) << 6) | ((w1.x >> 5) << 3) | (w1.y >> 5);
        int b2 = ((w1.z >> 5) << 6) | ((w1.w >> 5) << 3) | (w2.x >> 5);
        int b3 = ((w2.y >> 5) << 6) | ((w2.z >> 5) << 3) | (w2.w >> 5);
        atomicAdd(&sh[b0], 1);
        atomicAdd(&sh[b1], 1);
        atomicAdd(&sh[b2], 1);
        atomicAdd(&sh[b3], 1);
    }
    __syncthreads();

    float c0 = (float)sh[tid];
    float c1 = (float)sh[tid + 256];
    float s = c0*c0 + c1*c1;
    #pragma unroll
    for (int o = 16; o; o >>= 1) s += __shfl_xor_sync(0xffffffffu, s, o);
    if ((tid & 31) == 0) ssq[tid >> 5] = s;
    __syncthreads();
    if (tid < 8) {
        float v = ssq[tid];
        #pragma unroll
        for (int o = 4; o; o >>= 1) v += __shfl_xor_sync(0xffu, v, o);
        if (tid == 0) ssq[0] = v;
    }
    __syncthreads();

    float scale = 1.0f / fmaxf(sqrtf(ssq[0]), 1e-12f);
    __half* outp = g_hist + (long long)f * NBINS;
    outp[tid]       = __float2half(c0 * scale);
    outp[tid + 256] = __float2half(c1 * scale);
}

// ---------------------------------------------------------------------------
// Kernel 2: band sims + FC + ReLU on mma.sync fp16.
// Grid (37, 4) = 148 blocks (one full wave), 512 threads (16 warps).
// ---------------------------------------------------------------------------
#define SMEM_WIN_BYTES  (WROWS * WSTRIDE * 2)            // 133120
#define SMEM_SWIN_BYTES (32 * SW_STRIDE * 2)             // 7680
#define SMEM_FC_BYTES   (112 * FC_STRIDE * 2)            // 30464
#define SMEM_BIAS_BYTES (OUT_DIM * 4)
#define SMEM_TOTAL (SMEM_WIN_BYTES + SMEM_SWIN_BYTES + SMEM_FC_BYTES + SMEM_BIAS_BYTES)

__global__ __launch_bounds__(512, 1) void band_fc_kernel(
    const float* __restrict__ fc_w,
    const float* __restrict__ fc_b,
    float* __restrict__ out)
{
    extern __shared__ char smem[];
    __half* swh  = (__half*)smem;                                        // [128][520]
    __half* swin = (__half*)(smem + SMEM_WIN_BYTES);                     // [32][120]
    __half* sfc  = (__half*)(smem + SMEM_WIN_BYTES + SMEM_SWIN_BYTES);   // [112][136] natural [k][o]
    float*  sbias= (float*)(smem + SMEM_WIN_BYTES + SMEM_SWIN_BYTES + SMEM_FC_BYTES);

    const int tid  = threadIdx.x;
    const int warp = tid >> 5;
    const int lane = tid & 31;
    const int b    = blockIdx.y;
    const int t0   = blockIdx.x * TB;

    // ---- Phase 1a: issue all window cp.asyncs (fp16 rows, zfill OOB) ----
    const __half* hb = g_hist + (long long)b * TT * NBINS;
    {
        uint32_t sbase = smem_u32(swh);
        #pragma unroll
        for (int i = 0; i < 16; i++) {
            int idx = tid + i * 512;              // 128*64 = 8192 chunks
            int row   = idx >> 6;
            int chunk = idx & 63;
            int g = t0 - PAD + row;
            int inb = (g >= 0 && g < TT);
            const __half* gsrc = hb + ((long long)(inb ? g : 0) * NBINS) + chunk * 8;
            uint32_t sdst = sbase + (uint32_t)(row * (WSTRIDE*2) + chunk * 16);
            CP_ASYNC16(sdst, gsrc, inb ? 16 : 0);
        }
        asm volatile("cp.async.commit_group;");
    }

    // ---- Phase 1b (overlaps cp.async): fc weights, zeros, bias ----
    for (int idx = tid; idx < LOOKUP * 32; idx += 512) {
        int l  = idx >> 5;
        int o4 = idx & 31;
        float4 v = ((const float4*)(fc_w + l * OUT_DIM))[o4];
        __half2* dst = (__half2*)(sfc + l * FC_STRIDE + o4 * 4);
        dst[0] = __floats2half2_rn(v.x, v.y);
        dst[1] = __floats2half2_rn(v.z, v.w);
    }
    for (int idx = tid; idx < 11 * (FC_STRIDE/2); idx += 512) {
        int r = 101 + idx / (FC_STRIDE/2);
        int c = idx % (FC_STRIDE/2);
        ((__half2*)(sfc + r * FC_STRIDE))[c] = __half2half2(__float2half(0.f));
    }
    for (int idx = tid; idx < 32 * SW_STRIDE / 2; idx += 512)
        ((__half2*)swin)[idx] = __half2half2(__float2half(0.f));
    if (tid < OUT_DIM) sbias[tid] = fc_b[tid];

    asm volatile("cp.async.wait_group 0;");
    __syncthreads();

    // ---- Phase 2: GEMM1  C[32 x 128] = A[32x512] * W[128x512]^T ----
    // warp -> m-tile (warp>>3), n-tile pair ((warp&7)*2, +1)
    {
        const int mt = warp >> 3;
        const int np = (warp & 7) * 2;
        float acc[2][4];
        #pragma unroll
        for (int j = 0; j < 2; j++)
            #pragma unroll
            for (int i = 0; i < 4; i++) acc[j][i] = 0.f;

        uint32_t swh0 = smem_u32(swh);
        uint32_t a_base = swh0 +
            (uint32_t)(((mt*16 + (lane & 15) + PAD) * WSTRIDE + (lane >> 4) * 8) * 2);
        uint32_t b_base = swh0 + (uint32_t)(
            (((np + ((lane >> 4) & 1)) * 8 + (lane & 7)) * WSTRIDE
             + ((lane >> 3) & 1) * 8) * 2);

        #pragma unroll 4
        for (int kk = 0; kk < NBINS/16; kk++) {
            uint32_t a0,a1,a2,a3, q0,q1,q2,q3;
            LDSM_X4(a0,a1,a2,a3, a_base + kk*32);
            LDSM_X4(q0,q1,q2,q3, b_base + kk*32);
            MMA16816(acc[0], a0,a1,a2,a3, q0,q1);
            MMA16816(acc[1], a0,a1,a2,a3, q2,q3);
        }

        // band extraction: swin[r][wr - r] for 0 <= wr - r < 101
        int r0 = mt*16 + (lane >> 2);
        int cb = 2*(lane & 3);
        #pragma unroll
        for (int j = 0; j < 2; j++) {
            int c0 = (np + j)*8 + cb;
            int l;
            l = c0     - r0;     if ((unsigned)l < LOOKUP) swin[r0*SW_STRIDE + l]     = __float2half(acc[j][0]);
            l = c0 + 1 - r0;     if ((unsigned)l < LOOKUP) swin[r0*SW_STRIDE + l]     = __float2half(acc[j][1]);
            l = c0     - (r0+8); if ((unsigned)l < LOOKUP) swin[(r0+8)*SW_STRIDE + l] = __float2half(acc[j][2]);
            l = c0 + 1 - (r0+8); if ((unsigned)l < LOOKUP) swin[(r0+8)*SW_STRIDE + l] = __float2half(acc[j][3]);
        }
    }
    __syncthreads();

    // ---- Phase 3: GEMM2  O[32x128] = win[32x112] * fc[112x128]  (+bias, ReLU)
    {
        const int mt = warp >> 3;
        const int np = (warp & 7) * 2;
        float acc[2][4];
        #pragma unroll
        for (int j = 0; j < 2; j++)
            #pragma unroll
            for (int i = 0; i < 4; i++) acc[j][i] = 0.f;

        uint32_t a_base = smem_u32(swin) +
            (uint32_t)(((mt*16 + (lane & 15)) * SW_STRIDE + (lane >> 4) * 8) * 2);
        uint32_t b_base = smem_u32(sfc) + (uint32_t)(
            ((((lane >> 3) & 1) * 8 + (lane & 7)) * FC_STRIDE
             + (np + ((lane >> 4) & 1)) * 8) * 2);

        #pragma unroll
        for (int kk = 0; kk < 7; kk++) {       // K = 112
            uint32_t a0,a1,a2,a3, q0,q1,q2,q3;
            LDSM_X4(a0,a1,a2,a3, a_base + kk*32);
            LDSM_X4T(q0,q1,q2,q3, b_base + (uint32_t)(kk * 16 * FC_STRIDE * 2));
            MMA16816(acc[0], a0,a1,a2,a3, q0,q1);
            MMA16816(acc[1], a0,a1,a2,a3, q2,q3);
        }

        int r0 = mt*16 + (lane >> 2);
        int cb = 2*(lane & 3);
        bool ok0 = (r0     < TB) && (t0 + r0     < TT);
        bool ok1 = (r0 + 8 < TB) && (t0 + r0 + 8 < TT);
        float* obase = out + ((long long)(b * TT + t0 + r0)) * OUT_DIM;
        #pragma unroll
        for (int j = 0; j < 2; j++) {
            int c0 = (np + j)*8 + cb;
            float bv0 = sbias[c0], bv1 = sbias[c0 + 1];
            if (ok0) {
                float2 v0 = make_float2(fmaxf(acc[j][0] + bv0, 0.f), fmaxf(acc[j][1] + bv1, 0.f));
                *(float2*)(obase + c0) = v0;
            }
            if (ok1) {
                float2 v1 = make_float2(fmaxf(acc[j][2] + bv0, 0.f), fmaxf(acc[j][3] + bv1, 0.f));
                *(float2*)(obase + 8*OUT_DIM + c0) = v1;
            }
        }
    }
}

// ---------------------------------------------------------------------------
extern "C" void kernel_launch(void* const* d_in, const int* in_sizes, int n_in,
                              void* d_out, int out_size) {
    const int*   frames = (const int*)d_in[0];
    const float* fc_w   = (const float*)d_in[1];
    const float* fc_b   = (const float*)d_in[2];
    float* out = (float*)d_out;

    (void)in_sizes; (void)n_in; (void)out_size;

    cudaFuncSetAttribute(band_fc_kernel,
                         cudaFuncAttributeMaxDynamicSharedMemorySize, SMEM_TOTAL);

    hist_kernel<<<BB * TT, 256>>>(frames);
    band_fc_kernel<<<dim3(NCHUNK, BB), 512, SMEM_TOTAL>>>(fc_w, fc_b, out);
}

// round 6
// speedup vs baseline: 6.2840x; 1.0168x over previous
#include <cuda_runtime.h>
#include <cuda_fp16.h>
#include <cstdint>

#define BB 4
#define TT 1024
#define NPIX 1296
#define NBINS 512
#define LOOKUP 101
#define PAD 50
#define OUT_DIM 128
#define TB 28
#define NCHUNK 37        // ceil(1024/28)
#define WROWS 128        // TB + 2*PAD
#define WSTRIDE 520      // halves per window row (1040B)
#define SW_STRIDE 120    // halves per swin row
#define FC_STRIDE 136    // halves per sfc row / floats per partial row

// 4 MB scratch: normalized histograms in fp16 [B*T][NBINS]
__device__ __half g_hist[BB*TT*NBINS];

__device__ __forceinline__ uint32_t smem_u32(const void* p) {
    return (uint32_t)__cvta_generic_to_shared(p);
}

#define LDSM_X4(r0,r1,r2,r3,addr) \
    asm volatile("ldmatrix.sync.aligned.m8n8.x4.shared.b16 {%0,%1,%2,%3}, [%4];" \
        : "=r"(r0),"=r"(r1),"=r"(r2),"=r"(r3) : "r"(addr))
#define LDSM_X2T(r0,r1,addr) \
    asm volatile("ldmatrix.sync.aligned.m8n8.x2.trans.shared.b16 {%0,%1}, [%2];" \
        : "=r"(r0),"=r"(r1) : "r"(addr))
#define MMA16816(d, a0,a1,a2,a3, b0,b1) \
    asm volatile("mma.sync.aligned.m16n8k16.row.col.f32.f16.f16.f32 " \
        "{%0,%1,%2,%3}, {%4,%5,%6,%7}, {%8,%9}, {%0,%1,%2,%3};" \
        : "+f"(d[0]), "+f"(d[1]), "+f"(d[2]), "+f"(d[3]) \
        : "r"(a0),"r"(a1),"r"(a2),"r"(a3), "r"(b0),"r"(b1))
#define CP_ASYNC16(saddr, gaddr, srcsz) \
    asm volatile("cp.async.cg.shared.global [%0], [%1], 16, %2;" \
        :: "r"(saddr), "l"(gaddr), "r"(srcsz))

// ---------------------------------------------------------------------------
// Kernel 1: per-frame 512-bin histogram + L2 norm, fp16 output. (HBM roofline)
// ---------------------------------------------------------------------------
__global__ __launch_bounds__(256) void hist_kernel(const int* __restrict__ frames) {
    __shared__ int sh[NBINS];
    __shared__ float ssq[8];
    const int f = blockIdx.x;
    const int tid = threadIdx.x;

    sh[tid] = 0;
    sh[tid + 256] = 0;
    __syncthreads();

    const int4* fp4 = (const int4*)(frames + (long long)f * (NPIX * 3));
    for (int g = tid; g < NPIX/4; g += 256) {
        int4 w0 = __ldcs(&fp4[3*g + 0]);
        int4 w1 = __ldcs(&fp4[3*g + 1]);
        int4 w2 = __ldcs(&fp4[3*g + 2]);
        int b0 = ((w0.x >> 5) << 6) | ((w0.y >> 5) << 3) | (w0.z >> 5);
        int b1 = ((w0.w >> 5) << 6) | ((w1.x >> 5) << 3) | (w1.y >> 5);
        int b2 = ((w1.z >> 5) << 6) | ((w1.w >> 5) << 3) | (w2.x >> 5);
        int b3 = ((w2.y >> 5) << 6) | ((w2.z >> 5) << 3) | (w2.w >> 5);
        atomicAdd(&sh[b0], 1);
        atomicAdd(&sh[b1], 1);
        atomicAdd(&sh[b2], 1);
        atomicAdd(&sh[b3], 1);
    }
    __syncthreads();

    float c0 = (float)sh[tid];
    float c1 = (float)sh[tid + 256];
    float s = c0*c0 + c1*c1;
    #pragma unroll
    for (int o = 16; o; o >>= 1) s += __shfl_xor_sync(0xffffffffu, s, o);
    if ((tid & 31) == 0) ssq[tid >> 5] = s;
    __syncthreads();
    if (tid < 8) {
        float v = ssq[tid];
        #pragma unroll
        for (int o = 4; o; o >>= 1) v += __shfl_xor_sync(0xffu, v, o);
        if (tid == 0) ssq[0] = v;
    }
    __syncthreads();

    float scale = 1.0f / fmaxf(sqrtf(ssq[0]), 1e-12f);
    __half* outp = g_hist + (long long)f * NBINS;
    outp[tid]       = __float2half(c0 * scale);
    outp[tid + 256] = __float2half(c1 * scale);
}

// ---------------------------------------------------------------------------
// Kernel 2: band sims + FC + ReLU. 1024 threads, k-split warp specialization.
// Grid (37, 4) = 148 blocks.
// ---------------------------------------------------------------------------
#define SMEM_WIN_BYTES   (WROWS * WSTRIDE * 2)            // 133120
#define SMEM_PART_BYTES  (32 * FC_STRIDE * 4)             // 17408
#define SMEM_SWIN_BYTES  (32 * SW_STRIDE * 2)             // 7680
#define SMEM_FC_BYTES    (112 * FC_STRIDE * 2)            // 30464
#define SMEM_BIAS_BYTES  (OUT_DIM * 4)                    // 512
#define SMEM_TOTAL (SMEM_WIN_BYTES + SMEM_PART_BYTES + SMEM_SWIN_BYTES + SMEM_FC_BYTES + SMEM_BIAS_BYTES)

__global__ __launch_bounds__(1024, 1) void band_fc_kernel(
    const float* __restrict__ fc_w,
    const float* __restrict__ fc_b,
    float* __restrict__ out)
{
    extern __shared__ char smem[];
    __half* swh   = (__half*)smem;                                   // [128][520]
    float*  spart = (float*)(smem + SMEM_WIN_BYTES);                 // [32][136] fp32 partial C
    __half* swin  = (__half*)(smem + SMEM_WIN_BYTES + SMEM_PART_BYTES);               // [32][120]
    __half* sfc   = (__half*)(smem + SMEM_WIN_BYTES + SMEM_PART_BYTES + SMEM_SWIN_BYTES); // [112][136]
    float*  sbias = (float*)(smem + SMEM_WIN_BYTES + SMEM_PART_BYTES + SMEM_SWIN_BYTES + SMEM_FC_BYTES);

    const int tid   = threadIdx.x;
    const int warp  = tid >> 5;
    const int lane  = tid & 31;
    const int group = warp >> 4;          // 0: k-bins 0..255, 1: 256..511
    const int gtid  = tid & 511;
    const int b     = blockIdx.y;
    const int t0    = blockIdx.x * TB;

    // ---- Phase 1a: each group cp.asyncs ONLY its own k-half of the window ----
    const __half* hb = g_hist + (long long)b * TT * NBINS;
    {
        uint32_t sbase = smem_u32(swh);
        #pragma unroll
        for (int i = 0; i < 8; i++) {
            int idx   = gtid + i * 512;          // 128 rows x 32 chunks per half
            int row   = idx >> 5;
            int ch    = (idx & 31) + group * 32;
            int g = t0 - PAD + row;
            int inb = (g >= 0 && g < TT);
            const __half* gsrc = hb + ((long long)(inb ? g : 0) * NBINS) + ch * 8;
            uint32_t sdst = sbase + (uint32_t)(row * (WSTRIDE*2) + ch * 16);
            CP_ASYNC16(sdst, gsrc, inb ? 16 : 0);
        }
        asm volatile("cp.async.commit_group;");
    }

    // ---- Phase 1b (overlaps cp.async): fc weights, zeros, bias ----
    for (int idx = tid; idx < LOOKUP * 32; idx += 1024) {
        int l  = idx >> 5;
        int o4 = idx & 31;
        float4 v = ((const float4*)(fc_w + l * OUT_DIM))[o4];
        __half2* dst = (__half2*)(sfc + l * FC_STRIDE + o4 * 4);
        dst[0] = __floats2half2_rn(v.x, v.y);
        dst[1] = __floats2half2_rn(v.z, v.w);
    }
    // zero sfc k-pad rows 101..111
    for (int idx = tid; idx < 11 * (FC_STRIDE/2); idx += 1024) {
        int r = 101 + idx / (FC_STRIDE/2);
        int c = idx % (FC_STRIDE/2);
        ((__half2*)(sfc + r * FC_STRIDE))[c] = __half2half2(__float2half(0.f));
    }
    // zero swin k-pad cols 100..111 (col 100 later overwritten by extraction)
    for (int idx = tid; idx < 32 * 6; idx += 1024) {
        int r = idx / 6, c2 = idx % 6;
        *(__half2*)(swin + r * SW_STRIDE + 100 + 2*c2) = __half2half2(__float2half(0.f));
    }
    if (tid < OUT_DIM) sbias[tid] = fc_b[tid];

    // ---- wait own k-half only, group-scope barrier ----
    asm volatile("cp.async.wait_group 0;");
    asm volatile("bar.sync %0, 512;" :: "r"(group + 1));

    // ---- Phase 2: GEMM1 k-split. group g: k-iters g*16 .. g*16+15 ----
    const int wg = warp & 15;
    const int mt = wg >> 3;               // 0..1
    const int np = (wg & 7) * 2;          // n-tile pair
    float acc[2][4];
    #pragma unroll
    for (int j = 0; j < 2; j++)
        #pragma unroll
        for (int i = 0; i < 4; i++) acc[j][i] = 0.f;

    {
        uint32_t swh0 = smem_u32(swh);
        uint32_t a_base = swh0 +
            (uint32_t)(((mt*16 + (lane & 15) + PAD) * WSTRIDE + (lane >> 4) * 8) * 2)
            + (uint32_t)(group * 512);
        uint32_t b_base = swh0 + (uint32_t)(
            (((np + ((lane >> 4) & 1)) * 8 + (lane & 7)) * WSTRIDE
             + ((lane >> 3) & 1) * 8) * 2)
            + (uint32_t)(group * 512);

        #pragma unroll 4
        for (int kk = 0; kk < 16; kk++) {
            uint32_t a0,a1,a2,a3, q0,q1,q2,q3;
            LDSM_X4(a0,a1,a2,a3, a_base + kk*32);
            LDSM_X4(q0,q1,q2,q3, b_base + kk*32);
            MMA16816(acc[0], a0,a1,a2,a3, q0,q1);
            MMA16816(acc[1], a0,a1,a2,a3, q2,q3);
        }
    }

    int r0 = mt*16 + (lane >> 2);
    int cb = 2*(lane & 3);
    if (group == 0) {
        // dump partial C0 to smem
        #pragma unroll
        for (int j = 0; j < 2; j++) {
            int c0 = (np + j)*8 + cb;
            *(float2*)(spart + r0*FC_STRIDE + c0)     = make_float2(acc[j][0], acc[j][1]);
            *(float2*)(spart + (r0+8)*FC_STRIDE + c0) = make_float2(acc[j][2], acc[j][3]);
        }
    }
    __syncthreads();
    if (group == 1) {
        // combine with partial, extract band: swin[r][c-r], 0 <= c-r < 101
        #pragma unroll
        for (int j = 0; j < 2; j++) {
            int c0 = (np + j)*8 + cb;
            float2 p0 = *(float2*)(spart + r0*FC_STRIDE + c0);
            float2 p1 = *(float2*)(spart + (r0+8)*FC_STRIDE + c0);
            float v0 = acc[j][0] + p0.x, v1 = acc[j][1] + p0.y;
            float v2 = acc[j][2] + p1.x, v3 = acc[j][3] + p1.y;
            int l;
            l = c0     - r0;     if ((unsigned)l < LOOKUP) swin[r0*SW_STRIDE + l]     = __float2half(v0);
            l = c0 + 1 - r0;     if ((unsigned)l < LOOKUP) swin[r0*SW_STRIDE + l]     = __float2half(v1);
            l = c0     - (r0+8); if ((unsigned)l < LOOKUP) swin[(r0+8)*SW_STRIDE + l] = __float2half(v2);
            l = c0 + 1 - (r0+8); if ((unsigned)l < LOOKUP) swin[(r0+8)*SW_STRIDE + l] = __float2half(v3);
        }
    }
    __syncthreads();

    // ---- Phase 3: GEMM2  O[32x128] = win[32x112] * fc[112x128] (+bias, ReLU)
    // 32 warps: 2 m-tiles x 16 n-tiles
    {
        const int mt2 = warp >> 4;
        const int nt2 = warp & 15;
        float acc2[4];
        #pragma unroll
        for (int i = 0; i < 4; i++) acc2[i] = 0.f;

        uint32_t a_base = smem_u32(swin) +
            (uint32_t)(((mt2*16 + (lane & 15)) * SW_STRIDE + (lane >> 4) * 8) * 2);
        uint32_t b_base = smem_u32(sfc) +
            (uint32_t)(((lane & 15) * FC_STRIDE + nt2 * 8) * 2);

        #pragma unroll
        for (int kk = 0; kk < 7; kk++) {       // K = 112
            uint32_t a0,a1,a2,a3, q0,q1;
            LDSM_X4(a0,a1,a2,a3, a_base + kk*32);
            LDSM_X2T(q0,q1, b_base + (uint32_t)(kk * 16 * FC_STRIDE * 2));
            MMA16816(acc2, a0,a1,a2,a3, q0,q1);
        }

        int rr = mt2*16 + (lane >> 2);
        int c0 = nt2*8 + cb;
        bool ok0 = (rr     < TB) && (t0 + rr     < TT);
        bool ok1 = (rr + 8 < TB) && (t0 + rr + 8 < TT);
        float bv0 = sbias[c0], bv1 = sbias[c0 + 1];
        float* obase = out + ((long long)(b * TT + t0 + rr)) * OUT_DIM;
        if (ok0) {
            float2 v = make_float2(fmaxf(acc2[0] + bv0, 0.f), fmaxf(acc2[1] + bv1, 0.f));
            *(float2*)(obase + c0) = v;
        }
        if (ok1) {
            float2 v = make_float2(fmaxf(acc2[2] + bv0, 0.f), fmaxf(acc2[3] + bv1, 0.f));
            *(float2*)(obase + 8*OUT_DIM + c0) = v;
        }
    }
}

// ---------------------------------------------------------------------------
extern "C" void kernel_launch(void* const* d_in, const int* in_sizes, int n_in,
                              void* d_out, int out_size) {
    const int*   frames = (const int*)d_in[0];
    const float* fc_w   = (const float*)d_in[1];
    const float* fc_b   = (const float*)d_in[2];
    float* out = (float*)d_out;

    (void)in_sizes; (void)n_in; (void)out_size;

    cudaFuncSetAttribute(band_fc_kernel,
                         cudaFuncAttributeMaxDynamicSharedMemorySize, SMEM_TOTAL);

    hist_kernel<<<BB * TT, 256>>>(frames);
    band_fc_kernel<<<dim3(NCHUNK, BB), 1024, SMEM_TOTAL>>>(fc_w, fc_b, out);
}